// round 1
// baseline (speedup 1.0000x reference)
#include <cuda_runtime.h>
#include <math.h>

// Problem dims
#define T_  4
#define B_  32
#define C_  256
#define N_  1024     // H*W
#define EPS_ 1e-5f

// Scratch (allocation-free rule: __device__ globals)
__device__ float g_qlin[T_ * B_ * C_ * N_];   // 134 MB
__device__ float g_klin[T_ * B_ * C_ * N_];   // 134 MB
__device__ float g_xone[T_ * B_ * C_ * N_];   // 134 MB

// ---------------------------------------------------------------------------
// K1: batched GEMM (M=128-tile of 256, N=128-tile of 1024, K=256) + BN
//     grid: (ntile=8, {q0,q1,k0,k1}=4, batch=128), 256 threads, 8x8/thread
// ---------------------------------------------------------------------------
__global__ void __launch_bounds__(256) gemm_qk_kernel(
    const float* __restrict__ x,
    const float* __restrict__ q_w, const float* __restrict__ q_g,
    const float* __restrict__ q_be, const float* __restrict__ q_m,
    const float* __restrict__ q_v,
    const float* __restrict__ k_w, const float* __restrict__ k_g,
    const float* __restrict__ k_be, const float* __restrict__ k_m,
    const float* __restrict__ k_v)
{
    __shared__ float As[16][128];   // transposed weight tile: As[k][m]
    __shared__ float Bs[16][128];   // x tile: Bs[k][n]

    const int tid   = threadIdx.x;
    const int ntile = blockIdx.x;            // 0..7
    const int which = blockIdx.y >> 1;       // 0=q, 1=k
    const int obase = (blockIdx.y & 1) * 128;
    const int batch = blockIdx.z;            // t*B + b

    const float* w  = which ? k_w  : q_w;
    const float* gg = which ? k_g  : q_g;
    const float* bb = which ? k_be : q_be;
    const float* mm = which ? k_m  : q_m;
    const float* vv = which ? k_v  : q_v;
    float* outp     = which ? g_klin : g_qlin;

    const float* xb = x + (size_t)batch * C_ * N_ + ntile * 128;

    const int tx = tid & 15;   // col group: cols tx*4 and 64+tx*4
    const int ty = tid >> 4;   // row group: rows ty*4 and 64+ty*4

    float acc[2][2][4][4];
    #pragma unroll
    for (int a = 0; a < 2; ++a)
        #pragma unroll
        for (int bq = 0; bq < 2; ++bq)
            #pragma unroll
            for (int i = 0; i < 4; ++i)
                #pragma unroll
                for (int j = 0; j < 4; ++j)
                    acc[a][bq][i][j] = 0.0f;

    for (int kk = 0; kk < C_; kk += 16) {
        // load A tile (128 rows x 16 k), transpose into As[k][m]
        #pragma unroll
        for (int l = 0; l < 2; ++l) {
            int idx = tid + l * 256;      // 0..511 float4s
            int row = idx >> 2;           // 0..127
            int c4  = (idx & 3) * 4;      // 0,4,8,12
            float4 a = *(const float4*)(w + (size_t)(obase + row) * C_ + kk + c4);
            As[c4 + 0][row] = a.x;
            As[c4 + 1][row] = a.y;
            As[c4 + 2][row] = a.z;
            As[c4 + 3][row] = a.w;
        }
        // load B tile (16 k x 128 n)
        #pragma unroll
        for (int l = 0; l < 2; ++l) {
            int idx = tid + l * 256;
            int kr  = idx >> 5;           // 0..15
            int n4  = idx & 31;           // 0..31
            float4 bvec = *(const float4*)(xb + (size_t)(kk + kr) * N_ + n4 * 4);
            *(((float4*)&Bs[kr][0]) + n4) = bvec;
        }
        __syncthreads();

        #pragma unroll
        for (int k = 0; k < 16; ++k) {
            float4 a0 = *(const float4*)&As[k][ty * 4];
            float4 a1 = *(const float4*)&As[k][64 + ty * 4];
            float4 b0 = *(const float4*)&Bs[k][tx * 4];
            float4 b1 = *(const float4*)&Bs[k][64 + tx * 4];
            float av[2][4] = {{a0.x, a0.y, a0.z, a0.w}, {a1.x, a1.y, a1.z, a1.w}};
            float bv[2][4] = {{b0.x, b0.y, b0.z, b0.w}, {b1.x, b1.y, b1.z, b1.w}};
            #pragma unroll
            for (int ih = 0; ih < 2; ++ih)
                #pragma unroll
                for (int jh = 0; jh < 2; ++jh)
                    #pragma unroll
                    for (int i = 0; i < 4; ++i)
                        #pragma unroll
                        for (int j = 0; j < 4; ++j)
                            acc[ih][jh][i][j] += av[ih][i] * bv[jh][j];
        }
        __syncthreads();
    }

    // epilogue: BN (y*inv + (beta - mean*inv)) and store
    #pragma unroll
    for (int ih = 0; ih < 2; ++ih)
        #pragma unroll
        for (int i = 0; i < 4; ++i) {
            int o = obase + ih * 64 + ty * 4 + i;
            float inv = gg[o] / sqrtf(vv[o] + EPS_);
            float sh  = bb[o] - mm[o] * inv;
            float* orow = outp + ((size_t)batch * C_ + o) * N_ + ntile * 128;
            #pragma unroll
            for (int jh = 0; jh < 2; ++jh) {
                float4 r;
                r.x = acc[ih][jh][i][0] * inv + sh;
                r.y = acc[ih][jh][i][1] * inv + sh;
                r.z = acc[ih][jh][i][2] * inv + sh;
                r.w = acc[ih][jh][i][3] * inv + sh;
                *(float4*)(orow + jh * 64 + tx * 4) = r;
            }
        }
}

// ---------------------------------------------------------------------------
// K2: fused q-LIF, k-LIF, head channel-sum, attn-LIF (v_th=0.5), gating.
//     One thread owns one (b, head, n) and all dh=32 channels; time recurrence
//     entirely in registers. grid: (N/256=4, heads=8, B=32), 256 threads.
// ---------------------------------------------------------------------------
__global__ void __launch_bounds__(256) lif_attn_kernel()
{
    const int n = blockIdx.x * 256 + threadIdx.x;  // 0..1023
    const int h = blockIdx.y;                      // 0..7
    const int b = blockIdx.z;                      // 0..31

    float vq[32], vk[32];
    #pragma unroll
    for (int d = 0; d < 32; ++d) { vq[d] = 0.0f; vk[d] = 0.0f; }
    float va = 0.0f;

    #pragma unroll
    for (int t = 0; t < T_; ++t) {
        size_t base = ((size_t)(t * B_ + b) * C_ + h * 32) * N_ + n;
        float qs = 0.0f;
        unsigned kmask = 0u;
        #pragma unroll
        for (int d = 0; d < 32; ++d) {
            float q  = g_qlin[base + (size_t)d * N_];
            float v1 = vq[d] + (q - vq[d]) * 0.5f;
            bool  sq = (v1 >= 1.0f);
            qs += sq ? 1.0f : 0.0f;
            vq[d] = sq ? 0.0f : v1;

            float kx = g_klin[base + (size_t)d * N_];
            float v2 = vk[d] + (kx - vk[d]) * 0.5f;
            bool  sk = (v2 >= 1.0f);
            if (sk) kmask |= (1u << d);
            vk[d] = sk ? 0.0f : v2;
        }
        float va1 = va + (qs - va) * 0.5f;
        bool  sa  = (va1 >= 0.5f);
        va = sa ? 0.0f : va1;
        float am = sa ? 1.0f : 0.0f;
        #pragma unroll
        for (int d = 0; d < 32; ++d)
            g_xone[base + (size_t)d * N_] = ((kmask >> d) & 1u) ? am : 0.0f;
    }
}

// ---------------------------------------------------------------------------
// K3: projection GEMM (+bias, +BN) fused with final LIF over T.
//     Block owns a 128x64 (o x n) tile for one b, loops t with membrane
//     state in registers. grid: (N/64=16, 2, B=32), 256 threads, 8x4/thread.
// ---------------------------------------------------------------------------
__global__ void __launch_bounds__(256) proj_lif_kernel(
    const float* __restrict__ p_w, const float* __restrict__ p_b,
    const float* __restrict__ p_g, const float* __restrict__ p_be,
    const float* __restrict__ p_m, const float* __restrict__ p_v,
    float* __restrict__ out)
{
    __shared__ float As[16][128];
    __shared__ float Bs[16][64];

    const int tid   = threadIdx.x;
    const int ntile = blockIdx.x;        // 0..15
    const int obase = blockIdx.y * 128;  // 0 or 128
    const int b     = blockIdx.z;        // 0..31
    const int tx = tid & 15;             // cols tx*4..tx*4+3
    const int ty = tid >> 4;             // rows ty*4 and 64+ty*4

    float inv[2][4], sh[2][4], bias[2][4];
    #pragma unroll
    for (int ih = 0; ih < 2; ++ih)
        #pragma unroll
        for (int i = 0; i < 4; ++i) {
            int o = obase + ih * 64 + ty * 4 + i;
            float iv = p_g[o] / sqrtf(p_v[o] + EPS_);
            inv[ih][i]  = iv;
            sh[ih][i]   = p_be[o] - p_m[o] * iv;
            bias[ih][i] = p_b[o];
        }

    float vmem[2][4][4];
    #pragma unroll
    for (int ih = 0; ih < 2; ++ih)
        #pragma unroll
        for (int i = 0; i < 4; ++i)
            #pragma unroll
            for (int j = 0; j < 4; ++j)
                vmem[ih][i][j] = 0.0f;

    for (int t = 0; t < T_; ++t) {
        float acc[2][4][4];
        #pragma unroll
        for (int ih = 0; ih < 2; ++ih)
            #pragma unroll
            for (int i = 0; i < 4; ++i)
                #pragma unroll
                for (int j = 0; j < 4; ++j)
                    acc[ih][i][j] = 0.0f;

        const float* xb = g_xone + (size_t)(t * B_ + b) * C_ * N_ + ntile * 64;

        for (int kk = 0; kk < C_; kk += 16) {
            #pragma unroll
            for (int l = 0; l < 2; ++l) {
                int idx = tid + l * 256;
                int row = idx >> 2;
                int c4  = (idx & 3) * 4;
                float4 a = *(const float4*)(p_w + (size_t)(obase + row) * C_ + kk + c4);
                As[c4 + 0][row] = a.x;
                As[c4 + 1][row] = a.y;
                As[c4 + 2][row] = a.z;
                As[c4 + 3][row] = a.w;
            }
            {
                int kr = tid >> 4;    // 0..15
                int n4 = tid & 15;    // 0..15
                float4 bvec = *(const float4*)(xb + (size_t)(kk + kr) * N_ + n4 * 4);
                *(((float4*)&Bs[kr][0]) + n4) = bvec;
            }
            __syncthreads();

            #pragma unroll
            for (int k = 0; k < 16; ++k) {
                float4 a0 = *(const float4*)&As[k][ty * 4];
                float4 a1 = *(const float4*)&As[k][64 + ty * 4];
                float4 b0 = *(const float4*)&Bs[k][tx * 4];
                float av[2][4] = {{a0.x, a0.y, a0.z, a0.w}, {a1.x, a1.y, a1.z, a1.w}};
                float bv[4]    = {b0.x, b0.y, b0.z, b0.w};
                #pragma unroll
                for (int ih = 0; ih < 2; ++ih)
                    #pragma unroll
                    for (int i = 0; i < 4; ++i)
                        #pragma unroll
                        for (int j = 0; j < 4; ++j)
                            acc[ih][i][j] += av[ih][i] * bv[j];
            }
            __syncthreads();
        }

        // epilogue: +bias, BN, LIF step, write spikes
        #pragma unroll
        for (int ih = 0; ih < 2; ++ih)
            #pragma unroll
            for (int i = 0; i < 4; ++i) {
                int o = obase + ih * 64 + ty * 4 + i;
                float rr[4];
                #pragma unroll
                for (int j = 0; j < 4; ++j) {
                    float y  = acc[ih][i][j] + bias[ih][i];
                    y = y * inv[ih][i] + sh[ih][i];
                    float v1 = vmem[ih][i][j] + (y - vmem[ih][i][j]) * 0.5f;
                    bool  s  = (v1 >= 1.0f);
                    vmem[ih][i][j] = s ? 0.0f : v1;
                    rr[j] = s ? 1.0f : 0.0f;
                }
                float4 r = make_float4(rr[0], rr[1], rr[2], rr[3]);
                *(float4*)(out + ((size_t)(t * B_ + b) * C_ + o) * N_ + ntile * 64 + tx * 4) = r;
            }
    }
}

// ---------------------------------------------------------------------------
extern "C" void kernel_launch(void* const* d_in, const int* in_sizes, int n_in,
                              void* d_out, int out_size)
{
    (void)in_sizes; (void)n_in; (void)out_size;
    const float* x    = (const float*)d_in[0];
    const float* q_w  = (const float*)d_in[1];
    const float* q_g  = (const float*)d_in[2];
    const float* q_be = (const float*)d_in[3];
    const float* q_m  = (const float*)d_in[4];
    const float* q_v  = (const float*)d_in[5];
    const float* k_w  = (const float*)d_in[6];
    const float* k_g  = (const float*)d_in[7];
    const float* k_be = (const float*)d_in[8];
    const float* k_m  = (const float*)d_in[9];
    const float* k_v  = (const float*)d_in[10];
    const float* p_w  = (const float*)d_in[11];
    const float* p_b  = (const float*)d_in[12];
    const float* p_g  = (const float*)d_in[13];
    const float* p_be = (const float*)d_in[14];
    const float* p_m  = (const float*)d_in[15];
    const float* p_v  = (const float*)d_in[16];
    float* out = (float*)d_out;

    dim3 g1(8, 4, T_ * B_);
    gemm_qk_kernel<<<g1, 256>>>(x, q_w, q_g, q_be, q_m, q_v,
                                k_w, k_g, k_be, k_m, k_v);

    dim3 g2(N_ / 256, 8, B_);
    lif_attn_kernel<<<g2, 256>>>();

    dim3 g3(N_ / 64, 2, B_);
    proj_lif_kernel<<<g3, 256>>>(p_w, p_b, p_g, p_be, p_m, p_v, out);
}